// round 1
// baseline (speedup 1.0000x reference)
#include <cuda_runtime.h>
#include <cuda_bf16.h>
#include <cstddef>

#define TM 64
#define TN 128
#define TK 16
#define BN_EPS 1e-5f

// ---------------- static scratch (no allocations allowed) ----------------
__device__ float g_acc [30000 * 512];   // conv/GEMM accumulator
__device__ float g_bufA[30000 * 512];   // ping feature buffer (post BN+ReLU, concat)
__device__ float g_bufB[30000 * 512];   // pong feature buffer
__device__ float g_sum [512];
__device__ float g_sq  [512];
__device__ float g_scale[512];
__device__ float g_shift[512];

// ---------------- gather-GEMM-scatter (or dense GEMM) --------------------
// C-tile TM x TN, K-chunk TK, 256 threads, each thread 4x8 accumulators.
// in_idx == nullptr  -> identity gather (row m)
// out_idx == nullptr -> direct store (dense GEMM); else atomicAdd scatter.
__global__ __launch_bounds__(256) void gemm_gs_kernel(
    const float* __restrict__ A, const float* __restrict__ W,
    const int* __restrict__ in_idx, const int* __restrict__ out_idx,
    float* __restrict__ C,
    int M, int Cin, int Cout)
{
    __shared__ float As[TK][TM + 1];
    __shared__ float Bs[TK][TN];
    __shared__ int   rowIdx[TM];

    const int k     = blockIdx.z;
    const int mBase = blockIdx.x * TM;
    const int n0    = blockIdx.y * TN;
    const int tid   = threadIdx.x;
    const float* Wk = W + (size_t)k * Cin * Cout;

    if (tid < TM) {
        int g  = mBase + tid;
        int ri = -1;
        if (g < M) ri = in_idx ? in_idx[(size_t)k * M + g] : g;
        rowIdx[tid] = ri;
    }
    __syncthreads();

    const int ty = tid >> 4;       // 0..15 -> rows ty*4 .. ty*4+3
    const int tx = tid & 15;       // 0..15 -> cols tx*8 .. tx*8+7

    float acc[4][8];
#pragma unroll
    for (int i = 0; i < 4; i++)
#pragma unroll
        for (int j = 0; j < 8; j++) acc[i][j] = 0.f;

    // A-load mapping: one float4 per thread per chunk
    const int ar  = tid >> 2;            // 0..63 (smem row)
    const int av  = (tid & 3) * 4;       // 0,4,8,12 (col offset within chunk)
    int ariA      = rowIdx[ar];
    if (ariA < 0) ariA = 0;              // garbage row, scatter skipped later
    const float* arow = A + (size_t)ariA * Cin;

    for (int c0 = 0; c0 < Cin; c0 += TK) {
        // load A chunk (gathered), transposed into As[k][m]
        float4 a4 = *(const float4*)(arow + c0 + av);
        As[av + 0][ar] = a4.x;
        As[av + 1][ar] = a4.y;
        As[av + 2][ar] = a4.z;
        As[av + 3][ar] = a4.w;

        // load B chunk: TK x TN floats = 512 float4s, 2 per thread
#pragma unroll
        for (int i = tid; i < (TK * TN / 4); i += 256) {
            int kr = i >> 5;             // 0..15
            int c  = (i & 31) << 2;      // 0..124
            float4 b4 = make_float4(0.f, 0.f, 0.f, 0.f);
            if (n0 + c < Cout)
                b4 = *(const float4*)(Wk + (size_t)(c0 + kr) * Cout + n0 + c);
            *(float4*)&Bs[kr][c] = b4;
        }
        __syncthreads();

#pragma unroll
        for (int kk = 0; kk < TK; kk++) {
            float a0 = As[kk][ty * 4 + 0];
            float a1 = As[kk][ty * 4 + 1];
            float a2 = As[kk][ty * 4 + 2];
            float a3 = As[kk][ty * 4 + 3];
            float4 b0 = *(const float4*)&Bs[kk][tx * 8];
            float4 b1 = *(const float4*)&Bs[kk][tx * 8 + 4];
            acc[0][0] += a0 * b0.x; acc[0][1] += a0 * b0.y; acc[0][2] += a0 * b0.z; acc[0][3] += a0 * b0.w;
            acc[0][4] += a0 * b1.x; acc[0][5] += a0 * b1.y; acc[0][6] += a0 * b1.z; acc[0][7] += a0 * b1.w;
            acc[1][0] += a1 * b0.x; acc[1][1] += a1 * b0.y; acc[1][2] += a1 * b0.z; acc[1][3] += a1 * b0.w;
            acc[1][4] += a1 * b1.x; acc[1][5] += a1 * b1.y; acc[1][6] += a1 * b1.z; acc[1][7] += a1 * b1.w;
            acc[2][0] += a2 * b0.x; acc[2][1] += a2 * b0.y; acc[2][2] += a2 * b0.z; acc[2][3] += a2 * b0.w;
            acc[2][4] += a2 * b1.x; acc[2][5] += a2 * b1.y; acc[2][6] += a2 * b1.z; acc[2][7] += a2 * b1.w;
            acc[3][0] += a3 * b0.x; acc[3][1] += a3 * b0.y; acc[3][2] += a3 * b0.z; acc[3][3] += a3 * b0.w;
            acc[3][4] += a3 * b1.x; acc[3][5] += a3 * b1.y; acc[3][6] += a3 * b1.z; acc[3][7] += a3 * b1.w;
        }
        __syncthreads();
    }

    // epilogue
#pragma unroll
    for (int i = 0; i < 4; i++) {
        int r = ty * 4 + i;
        int g = mBase + r;
        if (g >= M) continue;
        if (out_idx) {
            int orow = out_idx[(size_t)k * M + g];
            float* crow = C + (size_t)orow * Cout;
#pragma unroll
            for (int j = 0; j < 8; j++) {
                int col = n0 + tx * 8 + j;
                if (col < Cout) atomicAdd(&crow[col], acc[i][j]);
            }
        } else {
            float* crow = C + (size_t)g * Cout;
#pragma unroll
            for (int j = 0; j < 8; j++) {
                int col = n0 + tx * 8 + j;
                if (col < Cout) crow[col] = acc[i][j];
            }
        }
    }
}

// ---------------- BN statistics: per-channel sum and sum-of-squares ------
__global__ void stats_kernel(const float* __restrict__ x, int N, int C,
                             float* __restrict__ sum, float* __restrict__ sq)
{
    extern __shared__ float s[];  // 2*C floats
    for (int i = threadIdx.x; i < 2 * C; i += blockDim.x) s[i] = 0.f;
    __syncthreads();

    size_t total = (size_t)N * C;
    for (size_t i = (size_t)blockIdx.x * blockDim.x + threadIdx.x; i < total;
         i += (size_t)gridDim.x * blockDim.x) {
        float v = x[i];
        int c = (int)(i % (size_t)C);
        atomicAdd(&s[c], v);
        atomicAdd(&s[C + c], v * v);
    }
    __syncthreads();
    for (int c = threadIdx.x; c < C; c += blockDim.x) {
        atomicAdd(&sum[c], s[c]);
        atomicAdd(&sq[c],  s[C + c]);
    }
}

__global__ void bnparam_kernel(const float* __restrict__ sum, const float* __restrict__ sq,
                               const float* __restrict__ gamma, const float* __restrict__ beta,
                               int N, int C,
                               float* __restrict__ scale, float* __restrict__ shift)
{
    int c = blockIdx.x * blockDim.x + threadIdx.x;
    if (c < C) {
        float invN = 1.f / (float)N;
        float m = sum[c] * invN;
        float v = sq[c] * invN - m * m;
        float sc = gamma[c] * rsqrtf(v + BN_EPS);
        scale[c] = sc;
        shift[c] = beta[c] - m * sc;
    }
}

// ---------------- normalize + ReLU into (possibly wider) concat buffer ---
__global__ void bnapply_kernel(const float* __restrict__ x, int N, int C, int ostride,
                               const float* __restrict__ scale, const float* __restrict__ shift,
                               float* __restrict__ out)
{
    size_t total = (size_t)N * C;
    for (size_t i = (size_t)blockIdx.x * blockDim.x + threadIdx.x; i < total;
         i += (size_t)gridDim.x * blockDim.x) {
        int c = (int)(i % (size_t)C);
        size_t r = i / (size_t)C;
        float v = fmaf(x[i], scale[c], shift[c]);
        out[r * (size_t)ostride + c] = fmaxf(v, 0.f);
    }
}

__global__ void copyskip_kernel(const float* __restrict__ f, int N, int Cf,
                                int ostride, int coff, float* __restrict__ out)
{
    size_t total = (size_t)N * Cf;
    for (size_t i = (size_t)blockIdx.x * blockDim.x + threadIdx.x; i < total;
         i += (size_t)gridDim.x * blockDim.x) {
        int c = (int)(i % (size_t)Cf);
        size_t r = i / (size_t)Cf;
        out[r * (size_t)ostride + coff + c] = f[i];
    }
}

// --------------------------------------------------------------------------
extern "C" void kernel_launch(void* const* d_in, const int* in_sizes, int n_in,
                              void* d_out, int out_size)
{
    (void)in_sizes; (void)n_in; (void)out_size;

    const float* f0    = (const float*)d_in[0];
    const float* f1    = (const float*)d_in[1];
    const float* f2    = (const float*)d_in[2];
    const float* f3    = (const float*)d_in[3];
    const float* W_up2 = (const float*)d_in[4];
    const float* W_up1 = (const float*)d_in[5];
    const float* W_up0 = (const float*)d_in[6];
    const float* W_s0  = (const float*)d_in[7];
    const float* W_s1  = (const float*)d_in[8];
    const float* W_s2  = (const float*)d_in[9];
    const float* g_up2 = (const float*)d_in[10]; const float* b_up2 = (const float*)d_in[11];
    const float* g_up1 = (const float*)d_in[12]; const float* b_up1 = (const float*)d_in[13];
    const float* g_up0 = (const float*)d_in[14]; const float* b_up0 = (const float*)d_in[15];
    const float* g_s0  = (const float*)d_in[16]; const float* b_s0  = (const float*)d_in[17];
    const float* g_s1  = (const float*)d_in[18]; const float* b_s1  = (const float*)d_in[19];
    const float* g_s2  = (const float*)d_in[20]; const float* b_s2  = (const float*)d_in[21];
    const int* up2_in = (const int*)d_in[22]; const int* up2_out = (const int*)d_in[23];
    const int* up1_in = (const int*)d_in[24]; const int* up1_out = (const int*)d_in[25];
    const int* up0_in = (const int*)d_in[26]; const int* up0_out = (const int*)d_in[27];
    const int* sm0_in = (const int*)d_in[28]; const int* sm0_out = (const int*)d_in[29];
    const int* sm1_in = (const int*)d_in[30]; const int* sm1_out = (const int*)d_in[31];

    float *acc, *bufA, *bufB, *sum, *sq, *scale, *shift;
    cudaGetSymbolAddress((void**)&acc,   g_acc);
    cudaGetSymbolAddress((void**)&bufA,  g_bufA);
    cudaGetSymbolAddress((void**)&bufB,  g_bufB);
    cudaGetSymbolAddress((void**)&sum,   g_sum);
    cudaGetSymbolAddress((void**)&sq,    g_sq);
    cudaGetSymbolAddress((void**)&scale, g_scale);
    cudaGetSymbolAddress((void**)&shift, g_shift);

    const int N0 = 30000, N1 = 12000, N2 = 5000;
    const int K = 27;

    auto layer = [&](const float* A, const float* W,
                     const int* ii, const int* oi,
                     int M, int Cin, int Cout, int Nout,
                     const float* gamma, const float* beta,
                     float* outbuf, int ostride,
                     const float* skip, int Cskip, int skip_N)
    {
        bool sparse = (oi != nullptr);
        if (sparse)
            cudaMemsetAsync(acc, 0, (size_t)Nout * Cout * sizeof(float), 0);
        cudaMemsetAsync(sum, 0, Cout * sizeof(float), 0);
        cudaMemsetAsync(sq,  0, Cout * sizeof(float), 0);

        dim3 grid((M + TM - 1) / TM, (Cout + TN - 1) / TN, sparse ? K : 1);
        gemm_gs_kernel<<<grid, 256, 0, 0>>>(A, W, ii, oi, acc, M, Cin, Cout);

        stats_kernel<<<592, 256, 2 * Cout * sizeof(float), 0>>>(acc, Nout, Cout, sum, sq);
        bnparam_kernel<<<2, 256, 0, 0>>>(sum, sq, gamma, beta, Nout, Cout, scale, shift);
        bnapply_kernel<<<592, 256, 0, 0>>>(acc, Nout, Cout, ostride, scale, shift, outbuf);
        if (skip)
            copyskip_kernel<<<256, 256, 0, 0>>>(skip, skip_N, Cskip, ostride, Cout, outbuf);
    };

    // up2: f3[2000,128] -> N2, Cout 128, concat f2(64) -> bufA[5000,192]
    layer(f3,   W_up2, up2_in, up2_out, 1600, 128, 128, N2, g_up2, b_up2, bufA, 192, f2, 64, N2);
    // up1: bufA[5000,192] -> N1, Cout 192, concat f1(32) -> bufB[12000,224]
    layer(bufA, W_up1, up1_in, up1_out, 4000, 192, 192, N1, g_up1, b_up1, bufB, 224, f1, 32, N1);
    // up0: bufB[12000,224] -> N0, Cout 224, concat f0(16) -> bufA[30000,240]
    layer(bufB, W_up0, up0_in, up0_out, 10000, 224, 224, N0, g_up0, b_up0, bufA, 240, f0, 16, N0);
    // s0: bufA[30000,240] -> N0, Cout 512 -> bufB
    layer(bufA, W_s0, sm0_in, sm0_out, 10000, 240, 512, N0, g_s0, b_s0, bufB, 512, nullptr, 0, 0);
    // s1: bufB[30000,512] -> N0, Cout 512 -> bufA
    layer(bufB, W_s1, sm1_in, sm1_out, 10000, 512, 512, N0, g_s1, b_s1, bufA, 512, nullptr, 0, 0);
    // s2: dense GEMM bufA[30000,512] @ W_s2[512,512] -> d_out
    layer(bufA, W_s2, nullptr, nullptr, N0, 512, 512, N0, g_s2, b_s2, (float*)d_out, 512, nullptr, 0, 0);
}

// round 5
// speedup vs baseline: 2.8876x; 2.8876x over previous
#include <cuda_runtime.h>
#include <cuda_bf16.h>
#include <cstdint>
#include <cstddef>

#define BN_EPS 1e-5f
#define KPAD 36

// ======================= static scratch (no allocs) =======================
__device__ float g_acc [30000 * 512];
__device__ float g_bufA[30000 * 512];
__device__ float g_bufB[30000 * 512];
__device__ float g_wt  [13450240];      // transposed weights pool
__device__ float g_sum [512];
__device__ float g_sq  [512];
__device__ float g_scale[512];
__device__ float g_shift[512];

// ======================= helpers =========================================
__device__ __forceinline__ float to_tf32(float x) {
    float y;
    asm("cvt.rna.tf32.f32 %0, %1;" : "=f"(y) : "f"(x));
    return y;
}
__device__ __forceinline__ void mma_tf32(float* d, const uint32_t* a, const uint32_t* b) {
    asm volatile(
        "mma.sync.aligned.m16n8k8.row.col.f32.tf32.tf32.f32 "
        "{%0,%1,%2,%3}, {%4,%5,%6,%7}, {%8,%9}, {%0,%1,%2,%3};"
        : "+f"(d[0]), "+f"(d[1]), "+f"(d[2]), "+f"(d[3])
        : "r"(a[0]), "r"(a[1]), "r"(a[2]), "r"(a[3]), "r"(b[0]), "r"(b[1]));
}
__device__ __forceinline__ void red_add_v2(float* p, float a, float b) {
    asm volatile("red.global.add.v2.f32 [%0], {%1, %2};"
                 :: "l"(p), "f"(a), "f"(b) : "memory");
}

// ======================= tensor-core gather-GEMM-scatter ==================
// CTA: 256 thr (8 warps 2x4), tile 128(M) x 128(N), K-chunks of 32.
// Warp tile 64x32 = 4x4 fragments of m16n8k8 tf32.
// in_idx==null -> identity gather; out_idx==null -> direct store (dense).
__global__ __launch_bounds__(256, 2) void mma_gs_kernel(
    const float* __restrict__ A, const float* __restrict__ WT,
    const int* __restrict__ in_idx, const int* __restrict__ out_idx,
    float* __restrict__ C, int M, int Cin, int Cout)
{
    __shared__ float As[128 * KPAD];
    __shared__ float Bs[128 * KPAD];
    __shared__ int   rowIdx[128];

    const int tid  = threadIdx.x;
    const int wid  = tid >> 5;
    const int lane = tid & 31;
    const int g8   = lane >> 2;    // group id 0..7
    const int t4   = lane & 3;     // thread-in-group 0..3

    const int k     = blockIdx.z;
    const int mBase = blockIdx.x * 128;
    const int n0    = blockIdx.y * 128;
    const float* WTk = WT + (size_t)k * Cout * Cin;

    const int warpM = (wid >> 2) * 64;     // 0 or 64
    const int warpN = (wid & 3) * 32;      // 0,32,64,96

    if (tid < 128) {
        int g = mBase + tid;
        int ri = 0;
        if (g < M) ri = in_idx ? in_idx[(size_t)k * M + g] : g;
        rowIdx[tid] = ri;
    }
    __syncthreads();

    float d[4][4][4];
#pragma unroll
    for (int mi = 0; mi < 4; mi++)
#pragma unroll
        for (int ni = 0; ni < 4; ni++)
#pragma unroll
            for (int r = 0; r < 4; r++) d[mi][ni][r] = 0.f;

    const int nc = (Cin + 31) >> 5;
    for (int c = 0; c < nc; ++c) {
        const int c0 = c << 5;
        // ---- load & tf32-convert A (gathered) and B chunk into smem ----
#pragma unroll
        for (int i = 0; i < 4; ++i) {
            int gi  = tid + i * 256;        // 0..1023
            int row = gi >> 3;              // 0..127
            int j   = gi & 7;               // float4 slot in 32-wide chunk
            int col = c0 + (j << 2);
            float4 av = make_float4(0.f, 0.f, 0.f, 0.f);
            if (col < Cin)
                av = *(const float4*)(A + (size_t)rowIdx[row] * Cin + col);
            float* ad = &As[row * KPAD + (j << 2)];
            ad[0] = to_tf32(av.x); ad[1] = to_tf32(av.y);
            ad[2] = to_tf32(av.z); ad[3] = to_tf32(av.w);

            float4 bv = make_float4(0.f, 0.f, 0.f, 0.f);
            if (col < Cin && (n0 + row) < Cout)
                bv = *(const float4*)(WTk + (size_t)(n0 + row) * Cin + col);
            float* bd = &Bs[row * KPAD + (j << 2)];
            bd[0] = to_tf32(bv.x); bd[1] = to_tf32(bv.y);
            bd[2] = to_tf32(bv.z); bd[3] = to_tf32(bv.w);
        }
        __syncthreads();

        // ---- 4 k8 steps of m16n8k8 mma ----
#pragma unroll
        for (int kk = 0; kk < 4; ++kk) {
            const int k0 = kk << 3;
            uint32_t a[4][4];
#pragma unroll
            for (int mi = 0; mi < 4; mi++) {
                int r = warpM + mi * 16 + g8;
                a[mi][0] = __float_as_uint(As[r * KPAD + k0 + t4]);
                a[mi][1] = __float_as_uint(As[(r + 8) * KPAD + k0 + t4]);
                a[mi][2] = __float_as_uint(As[r * KPAD + k0 + t4 + 4]);
                a[mi][3] = __float_as_uint(As[(r + 8) * KPAD + k0 + t4 + 4]);
            }
            uint32_t b[4][2];
#pragma unroll
            for (int ni = 0; ni < 4; ni++) {
                int n = warpN + ni * 8 + g8;
                b[ni][0] = __float_as_uint(Bs[n * KPAD + k0 + t4]);
                b[ni][1] = __float_as_uint(Bs[n * KPAD + k0 + t4 + 4]);
            }
#pragma unroll
            for (int mi = 0; mi < 4; mi++)
#pragma unroll
                for (int ni = 0; ni < 4; ni++)
                    mma_tf32(d[mi][ni], a[mi], b[ni]);
        }
        __syncthreads();
    }

    // ---- epilogue: scatter-add (sparse) or direct store (dense) ----
#pragma unroll
    for (int mi = 0; mi < 4; mi++) {
        int r0 = mBase + warpM + mi * 16 + g8;      // rows r0, r0+8
#pragma unroll
        for (int half = 0; half < 2; half++) {
            int rr = r0 + half * 8;
            if (rr >= M) continue;
            size_t orow = out_idx ? (size_t)out_idx[(size_t)k * M + rr] : (size_t)rr;
            float* crow = C + orow * Cout;
#pragma unroll
            for (int ni = 0; ni < 4; ni++) {
                int col = n0 + warpN + ni * 8 + t4 * 2;
                if (col + 1 < Cout) {
                    float v0 = d[mi][ni][half * 2 + 0];
                    float v1 = d[mi][ni][half * 2 + 1];
                    if (out_idx) red_add_v2(crow + col, v0, v1);
                    else        *(float2*)(crow + col) = make_float2(v0, v1);
                }
            }
        }
    }
}

// ======================= weight transpose [K][Cin][Cout] -> [K][Cout][Cin]
__global__ void transpose_kernel(const float* __restrict__ in, float* __restrict__ out,
                                 int R, int Ccol)
{
    __shared__ float t[32][33];
    const size_t koff = (size_t)blockIdx.z * R * Ccol;
    const float* ink = in + koff;
    float* outk = out + koff;
    int c0 = blockIdx.x * 32, r0 = blockIdx.y * 32;
    for (int i = threadIdx.y; i < 32; i += 8) {
        int r = r0 + i, c = c0 + threadIdx.x;
        t[i][threadIdx.x] = (r < R && c < Ccol) ? ink[(size_t)r * Ccol + c] : 0.f;
    }
    __syncthreads();
    for (int i = threadIdx.y; i < 32; i += 8) {
        int cc = c0 + i, rr = r0 + threadIdx.x;
        if (cc < Ccol && rr < R) outk[(size_t)cc * R + rr] = t[threadIdx.x][i];
    }
}

// ======================= BN kernels ======================================
__global__ void stats_kernel(const float* __restrict__ x, int N, int C,
                             float* __restrict__ sum, float* __restrict__ sq)
{
    extern __shared__ float s[];
    for (int i = threadIdx.x; i < 2 * C; i += blockDim.x) s[i] = 0.f;
    __syncthreads();
    size_t total = (size_t)N * C;
    for (size_t i = (size_t)blockIdx.x * blockDim.x + threadIdx.x; i < total;
         i += (size_t)gridDim.x * blockDim.x) {
        float v = x[i];
        int c = (int)(i % (size_t)C);
        atomicAdd(&s[c], v);
        atomicAdd(&s[C + c], v * v);
    }
    __syncthreads();
    for (int c = threadIdx.x; c < C; c += blockDim.x) {
        atomicAdd(&sum[c], s[c]);
        atomicAdd(&sq[c],  s[C + c]);
    }
}

__global__ void bnparam_kernel(const float* __restrict__ sum, const float* __restrict__ sq,
                               const float* __restrict__ gamma, const float* __restrict__ beta,
                               int N, int C,
                               float* __restrict__ scale, float* __restrict__ shift)
{
    int c = blockIdx.x * blockDim.x + threadIdx.x;
    if (c < C) {
        float invN = 1.f / (float)N;
        float m = sum[c] * invN;
        float v = sq[c] * invN - m * m;
        float sc = gamma[c] * rsqrtf(v + BN_EPS);
        scale[c] = sc;
        shift[c] = beta[c] - m * sc;
    }
}

__global__ void bnapply_kernel(const float* __restrict__ x, int N, int C, int ostride,
                               const float* __restrict__ scale, const float* __restrict__ shift,
                               float* __restrict__ out)
{
    size_t total = (size_t)N * C;
    for (size_t i = (size_t)blockIdx.x * blockDim.x + threadIdx.x; i < total;
         i += (size_t)gridDim.x * blockDim.x) {
        int c = (int)(i % (size_t)C);
        size_t r = i / (size_t)C;
        float v = fmaf(x[i], scale[c], shift[c]);
        out[r * (size_t)ostride + c] = fmaxf(v, 0.f);
    }
}

__global__ void copyskip_kernel(const float* __restrict__ f, int N, int Cf,
                                int ostride, int coff, float* __restrict__ out)
{
    size_t total = (size_t)N * Cf;
    for (size_t i = (size_t)blockIdx.x * blockDim.x + threadIdx.x; i < total;
         i += (size_t)gridDim.x * blockDim.x) {
        int c = (int)(i % (size_t)Cf);
        size_t r = i / (size_t)Cf;
        out[r * (size_t)ostride + coff + c] = f[i];
    }
}

// ==========================================================================
extern "C" void kernel_launch(void* const* d_in, const int* in_sizes, int n_in,
                              void* d_out, int out_size)
{
    (void)in_sizes; (void)n_in; (void)out_size;

    const float* f0    = (const float*)d_in[0];
    const float* f1    = (const float*)d_in[1];
    const float* f2    = (const float*)d_in[2];
    const float* f3    = (const float*)d_in[3];
    const float* W_up2 = (const float*)d_in[4];
    const float* W_up1 = (const float*)d_in[5];
    const float* W_up0 = (const float*)d_in[6];
    const float* W_s0  = (const float*)d_in[7];
    const float* W_s1  = (const float*)d_in[8];
    const float* W_s2  = (const float*)d_in[9];
    const float* g_up2 = (const float*)d_in[10]; const float* b_up2 = (const float*)d_in[11];
    const float* g_up1 = (const float*)d_in[12]; const float* b_up1 = (const float*)d_in[13];
    const float* g_up0 = (const float*)d_in[14]; const float* b_up0 = (const float*)d_in[15];
    const float* g_s0  = (const float*)d_in[16]; const float* b_s0  = (const float*)d_in[17];
    const float* g_s1  = (const float*)d_in[18]; const float* b_s1  = (const float*)d_in[19];
    const float* g_s2  = (const float*)d_in[20]; const float* b_s2  = (const float*)d_in[21];
    const int* up2_in = (const int*)d_in[22]; const int* up2_out = (const int*)d_in[23];
    const int* up1_in = (const int*)d_in[24]; const int* up1_out = (const int*)d_in[25];
    const int* up0_in = (const int*)d_in[26]; const int* up0_out = (const int*)d_in[27];
    const int* sm0_in = (const int*)d_in[28]; const int* sm0_out = (const int*)d_in[29];
    const int* sm1_in = (const int*)d_in[30]; const int* sm1_out = (const int*)d_in[31];

    float *acc, *bufA, *bufB, *wt, *sum, *sq, *scale, *shift;
    cudaGetSymbolAddress((void**)&acc,   g_acc);
    cudaGetSymbolAddress((void**)&bufA,  g_bufA);
    cudaGetSymbolAddress((void**)&bufB,  g_bufB);
    cudaGetSymbolAddress((void**)&wt,    g_wt);
    cudaGetSymbolAddress((void**)&sum,   g_sum);
    cudaGetSymbolAddress((void**)&sq,    g_sq);
    cudaGetSymbolAddress((void**)&scale, g_scale);
    cudaGetSymbolAddress((void**)&shift, g_shift);

    const int N0 = 30000, N1 = 12000, N2 = 5000;
    const int K = 27;

    // --- transpose all weights into pool ---
    float* wt_up2 = wt;
    float* wt_up1 = wt_up2 + (size_t)27 * 128 * 128;
    float* wt_up0 = wt_up1 + (size_t)27 * 192 * 192;
    float* wt_s0  = wt_up0 + (size_t)27 * 224 * 224;
    float* wt_s1  = wt_s0  + (size_t)27 * 240 * 512;
    float* wt_s2  = wt_s1  + (size_t)27 * 512 * 512;

    auto tlaunch = [&](const float* W, float* WT, int Cin, int Cout, int kk) {
        dim3 tg((Cout + 31) / 32, (Cin + 31) / 32, kk);
        transpose_kernel<<<tg, dim3(32, 8), 0, 0>>>(W, WT, Cin, Cout);
    };
    tlaunch(W_up2, wt_up2, 128, 128, K);
    tlaunch(W_up1, wt_up1, 192, 192, K);
    tlaunch(W_up0, wt_up0, 224, 224, K);
    tlaunch(W_s0,  wt_s0,  240, 512, K);
    tlaunch(W_s1,  wt_s1,  512, 512, K);
    tlaunch(W_s2,  wt_s2,  512, 512, 1);

    auto layer = [&](const float* A, const float* WT,
                     const int* ii, const int* oi,
                     int M, int Cin, int Cout, int Nout,
                     const float* gamma, const float* beta,
                     float* outbuf, int ostride,
                     const float* skip, int Cskip, int skip_N)
    {
        bool sparse = (oi != nullptr);
        float* dst = sparse ? acc : outbuf;   // dense final layer stores direct
        if (sparse)
            cudaMemsetAsync(acc, 0, (size_t)Nout * Cout * sizeof(float), 0);
        cudaMemsetAsync(sum, 0, Cout * sizeof(float), 0);
        cudaMemsetAsync(sq,  0, Cout * sizeof(float), 0);

        dim3 grid((M + 127) / 128, (Cout + 127) / 128, sparse ? K : 1);
        mma_gs_kernel<<<grid, 256, 0, 0>>>(A, WT, ii, oi, dst, M, Cin, Cout);

        stats_kernel<<<592, 256, 2 * Cout * sizeof(float), 0>>>(dst, Nout, Cout, sum, sq);
        bnparam_kernel<<<2, 256, 0, 0>>>(sum, sq, gamma, beta, Nout, Cout, scale, shift);
        bnapply_kernel<<<592, 256, 0, 0>>>(dst, Nout, Cout, ostride, scale, shift, outbuf);
        if (skip)
            copyskip_kernel<<<256, 256, 0, 0>>>(skip, skip_N, Cskip, ostride, Cout, outbuf);
    };

    // up2: f3 -> N2 (Cout 128), concat f2(64) -> bufA[5000,192]
    layer(f3,   wt_up2, up2_in, up2_out, 1600, 128, 128, N2, g_up2, b_up2, bufA, 192, f2, 64, N2);
    // up1: bufA -> N1 (Cout 192), concat f1(32) -> bufB[12000,224]
    layer(bufA, wt_up1, up1_in, up1_out, 4000, 192, 192, N1, g_up1, b_up1, bufB, 224, f1, 32, N1);
    // up0: bufB -> N0 (Cout 224), concat f0(16) -> bufA[30000,240]
    layer(bufB, wt_up0, up0_in, up0_out, 10000, 224, 224, N0, g_up0, b_up0, bufA, 240, f0, 16, N0);
    // s0: bufA[30000,240] -> N0 (Cout 512) -> bufB
    layer(bufA, wt_s0, sm0_in, sm0_out, 10000, 240, 512, N0, g_s0, b_s0, bufB, 512, nullptr, 0, 0);
    // s1: bufB -> N0 (Cout 512) -> bufA
    layer(bufB, wt_s1, sm1_in, sm1_out, 10000, 512, 512, N0, g_s1, b_s1, bufA, 512, nullptr, 0, 0);
    // s2: dense GEMM bufA @ W_s2 -> d_out
    layer(bufA, wt_s2, nullptr, nullptr, N0, 512, 512, N0, g_s2, b_s2, (float*)d_out, 512, nullptr, 0, 0);
}

// round 6
// speedup vs baseline: 3.6077x; 1.2494x over previous
#include <cuda_runtime.h>
#include <cuda_bf16.h>
#include <cstdint>
#include <cstddef>

#define BN_EPS 1e-5f
#define SROW 40

// ======================= static scratch (no allocs) =======================
__device__ float g_acc [30000 * 512];
__device__ float g_bufA[30000 * 512];
__device__ float g_bufB[30000 * 512];
__device__ float g_wt  [13450240];      // transposed weights pool
__device__ float g_sum [512];
__device__ float g_sq  [512];
__device__ float g_scale[512];
__device__ float g_shift[512];

// ======================= helpers =========================================
__device__ __forceinline__ float to_tf32(float x) {
    float y;
    asm("cvt.rna.tf32.f32 %0, %1;" : "=f"(y) : "f"(x));
    return y;
}
__device__ __forceinline__ void mma_tf32(float* d, const uint32_t* a, const uint32_t* b) {
    asm volatile(
        "mma.sync.aligned.m16n8k8.row.col.f32.tf32.tf32.f32 "
        "{%0,%1,%2,%3}, {%4,%5,%6,%7}, {%8,%9}, {%0,%1,%2,%3};"
        : "+f"(d[0]), "+f"(d[1]), "+f"(d[2]), "+f"(d[3])
        : "r"(a[0]), "r"(a[1]), "r"(a[2]), "r"(a[3]), "r"(b[0]), "r"(b[1]));
}
__device__ __forceinline__ void red_add_v2(float* p, float a, float b) {
    asm volatile("red.global.add.v2.f32 [%0], {%1, %2};"
                 :: "l"(p), "f"(a), "f"(b) : "memory");
}

// ======================= tensor-core gather-GEMM-scatter ==================
// CTA: 256 thr (8 warps 2x4), tile 128(M) x 128(N), K-chunks of 32.
// Pair-interleaved XOR-swizzled smem: element (row, k) with k = kk*8 + k3
// stored at row*SROW + kk*8 + ((2*(k3&3) + (k3>>2)) ^ ((row<<1)&6)).
// Fragment loads become conflict-free LDS.64; scalar stores conflict-free.
__global__ __launch_bounds__(256, 2) void mma_gs_kernel(
    const float* __restrict__ A, const float* __restrict__ WT,
    const int* __restrict__ in_idx, const int* __restrict__ out_idx,
    float* __restrict__ C, int M, int Cin, int Cout)
{
    __shared__ float As[128 * SROW];
    __shared__ float Bs[128 * SROW];
    __shared__ int   rowIdx[128];

    const int tid  = threadIdx.x;
    const int wid  = tid >> 5;
    const int lane = tid & 31;
    const int g8   = lane >> 2;
    const int t4   = lane & 3;

    const int k     = blockIdx.z;
    const int mBase = blockIdx.x * 128;
    const int n0    = blockIdx.y * 128;
    const float* WTk = WT + (size_t)k * Cout * Cin;

    const int warpM = (wid >> 2) * 64;
    const int warpN = (wid & 3) * 32;

    if (tid < 128) {
        int g = mBase + tid;
        int ri = 0;
        if (g < M) ri = in_idx ? in_idx[(size_t)k * M + g] : g;
        rowIdx[tid] = ri;
    }
    __syncthreads();

    // cached per-thread A source pointers (include 4j column offset)
    const float* aptr[4];
    {
#pragma unroll
        for (int s = 0; s < 4; ++s) {
            int gi = tid + s * 256;
            int row = gi >> 3, j = gi & 7;
            aptr[s] = A + (size_t)rowIdx[row] * Cin + 4 * j;
        }
    }

    float d[4][4][4];
#pragma unroll
    for (int mi = 0; mi < 4; mi++)
#pragma unroll
        for (int ni = 0; ni < 4; ni++)
#pragma unroll
            for (int r = 0; r < 4; r++) d[mi][ni][r] = 0.f;

    const int nc = (Cin + 31) >> 5;

    // prologue: prefetch A chunk 0 into registers
    float4 pav[4];
#pragma unroll
    for (int s = 0; s < 4; ++s) {
        int gi = tid + s * 256;
        int j = gi & 7;
        pav[s] = make_float4(0.f, 0.f, 0.f, 0.f);
        if (4 * j < Cin) pav[s] = *(const float4*)(aptr[s]);
    }

    for (int c = 0; c < nc; ++c) {
        const int c0 = c << 5;

        // ---- store prefetched A + load/store B into swizzled smem ----
#pragma unroll
        for (int s = 0; s < 4; ++s) {
            int gi  = tid + s * 256;
            int row = gi >> 3, j = gi & 7;
            int e    = (row << 1) & 6;
            int base = row * SROW + (j >> 1) * 8;
            int o    = j & 1;
            float4 av = pav[s];
            As[base + ((0 + o) ^ e)] = to_tf32(av.x);
            As[base + ((2 + o) ^ e)] = to_tf32(av.y);
            As[base + ((4 + o) ^ e)] = to_tf32(av.z);
            As[base + ((6 + o) ^ e)] = to_tf32(av.w);

            int col = c0 + 4 * j;
            float4 bv = make_float4(0.f, 0.f, 0.f, 0.f);
            if (col < Cin && (n0 + row) < Cout)
                bv = *(const float4*)(WTk + (size_t)(n0 + row) * Cin + col);
            Bs[base + ((0 + o) ^ e)] = to_tf32(bv.x);
            Bs[base + ((2 + o) ^ e)] = to_tf32(bv.y);
            Bs[base + ((4 + o) ^ e)] = to_tf32(bv.z);
            Bs[base + ((6 + o) ^ e)] = to_tf32(bv.w);
        }
        __syncthreads();

        // ---- prefetch A chunk c+1 (completes under the MMA block) ----
        if (c + 1 < nc) {
            const int c1 = c0 + 32;
#pragma unroll
            for (int s = 0; s < 4; ++s) {
                int gi = tid + s * 256;
                int j = gi & 7;
                int col = c1 + 4 * j;
                pav[s] = make_float4(0.f, 0.f, 0.f, 0.f);
                if (col < Cin) pav[s] = *(const float4*)(aptr[s] + c1);
            }
        }

        // ---- 4 k8 MMA steps, conflict-free LDS.64 fragment loads ----
#pragma unroll
        for (int kk = 0; kk < 4; ++kk) {
            const int kb = kk << 3;
            uint32_t a[4][4];
#pragma unroll
            for (int mi = 0; mi < 4; mi++) {
                int r = warpM + mi * 16 + g8;
                int e = (r << 1) & 6;
                int off = r * SROW + kb + ((2 * t4) ^ e);
                float2 v0 = *(const float2*)&As[off];
                float2 v1 = *(const float2*)&As[off + 8 * SROW];
                a[mi][0] = __float_as_uint(v0.x);
                a[mi][2] = __float_as_uint(v0.y);
                a[mi][1] = __float_as_uint(v1.x);
                a[mi][3] = __float_as_uint(v1.y);
            }
            uint32_t b[4][2];
#pragma unroll
            for (int ni = 0; ni < 4; ni++) {
                int n = warpN + ni * 8 + g8;
                int e = (n << 1) & 6;
                float2 w = *(const float2*)&Bs[n * SROW + kb + ((2 * t4) ^ e)];
                b[ni][0] = __float_as_uint(w.x);
                b[ni][1] = __float_as_uint(w.y);
            }
#pragma unroll
            for (int mi = 0; mi < 4; mi++)
#pragma unroll
                for (int ni = 0; ni < 4; ni++)
                    mma_tf32(d[mi][ni], a[mi], b[ni]);
        }
        __syncthreads();
    }

    // ---- epilogue: scatter-add (sparse) or direct store (dense) ----
#pragma unroll
    for (int mi = 0; mi < 4; mi++) {
        int r0 = mBase + warpM + mi * 16 + g8;
#pragma unroll
        for (int half = 0; half < 2; half++) {
            int rr = r0 + half * 8;
            if (rr >= M) continue;
            size_t orow = out_idx ? (size_t)out_idx[(size_t)k * M + rr] : (size_t)rr;
            float* crow = C + orow * Cout;
#pragma unroll
            for (int ni = 0; ni < 4; ni++) {
                int col = n0 + warpN + ni * 8 + t4 * 2;
                if (col + 1 < Cout) {
                    float v0 = d[mi][ni][half * 2 + 0];
                    float v1 = d[mi][ni][half * 2 + 1];
                    if (out_idx) red_add_v2(crow + col, v0, v1);
                    else        *(float2*)(crow + col) = make_float2(v0, v1);
                }
            }
        }
    }
}

// ======================= weight transpose [K][Cin][Cout] -> [K][Cout][Cin]
__global__ void transpose_kernel(const float* __restrict__ in, float* __restrict__ out,
                                 int R, int Ccol)
{
    __shared__ float t[32][33];
    const size_t koff = (size_t)blockIdx.z * R * Ccol;
    const float* ink = in + koff;
    float* outk = out + koff;
    int c0 = blockIdx.x * 32, r0 = blockIdx.y * 32;
    for (int i = threadIdx.y; i < 32; i += 8) {
        int r = r0 + i, c = c0 + threadIdx.x;
        t[i][threadIdx.x] = (r < R && c < Ccol) ? ink[(size_t)r * Ccol + c] : 0.f;
    }
    __syncthreads();
    for (int i = threadIdx.y; i < 32; i += 8) {
        int cc = c0 + i, rr = r0 + threadIdx.x;
        if (cc < Ccol && rr < R) outk[(size_t)cc * R + rr] = t[threadIdx.x][i];
    }
}

// ======================= BN kernels ======================================
__global__ void stats_kernel(const float* __restrict__ x, int N, int C,
                             float* __restrict__ sum, float* __restrict__ sq)
{
    extern __shared__ float s[];
    for (int i = threadIdx.x; i < 2 * C; i += blockDim.x) s[i] = 0.f;
    __syncthreads();
    size_t total = (size_t)N * C;
    for (size_t i = (size_t)blockIdx.x * blockDim.x + threadIdx.x; i < total;
         i += (size_t)gridDim.x * blockDim.x) {
        float v = x[i];
        int c = (int)(i % (size_t)C);
        atomicAdd(&s[c], v);
        atomicAdd(&s[C + c], v * v);
    }
    __syncthreads();
    for (int c = threadIdx.x; c < C; c += blockDim.x) {
        atomicAdd(&sum[c], s[c]);
        atomicAdd(&sq[c],  s[C + c]);
    }
}

__global__ void bnparam_kernel(const float* __restrict__ sum, const float* __restrict__ sq,
                               const float* __restrict__ gamma, const float* __restrict__ beta,
                               int N, int C,
                               float* __restrict__ scale, float* __restrict__ shift)
{
    int c = blockIdx.x * blockDim.x + threadIdx.x;
    if (c < C) {
        float invN = 1.f / (float)N;
        float m = sum[c] * invN;
        float v = sq[c] * invN - m * m;
        float sc = gamma[c] * rsqrtf(v + BN_EPS);
        scale[c] = sc;
        shift[c] = beta[c] - m * sc;
    }
}

__global__ void bnapply_kernel(const float* __restrict__ x, int N, int C, int ostride,
                               const float* __restrict__ scale, const float* __restrict__ shift,
                               float* __restrict__ out)
{
    size_t total = (size_t)N * C;
    for (size_t i = (size_t)blockIdx.x * blockDim.x + threadIdx.x; i < total;
         i += (size_t)gridDim.x * blockDim.x) {
        int c = (int)(i % (size_t)C);
        size_t r = i / (size_t)C;
        float v = fmaf(x[i], scale[c], shift[c]);
        out[r * (size_t)ostride + c] = fmaxf(v, 0.f);
    }
}

__global__ void copyskip_kernel(const float* __restrict__ f, int N, int Cf,
                                int ostride, int coff, float* __restrict__ out)
{
    size_t total = (size_t)N * Cf;
    for (size_t i = (size_t)blockIdx.x * blockDim.x + threadIdx.x; i < total;
         i += (size_t)gridDim.x * blockDim.x) {
        int c = (int)(i % (size_t)Cf);
        size_t r = i / (size_t)Cf;
        out[r * (size_t)ostride + coff + c] = f[i];
    }
}

// ==========================================================================
extern "C" void kernel_launch(void* const* d_in, const int* in_sizes, int n_in,
                              void* d_out, int out_size)
{
    (void)in_sizes; (void)n_in; (void)out_size;

    const float* f0    = (const float*)d_in[0];
    const float* f1    = (const float*)d_in[1];
    const float* f2    = (const float*)d_in[2];
    const float* f3    = (const float*)d_in[3];
    const float* W_up2 = (const float*)d_in[4];
    const float* W_up1 = (const float*)d_in[5];
    const float* W_up0 = (const float*)d_in[6];
    const float* W_s0  = (const float*)d_in[7];
    const float* W_s1  = (const float*)d_in[8];
    const float* W_s2  = (const float*)d_in[9];
    const float* g_up2 = (const float*)d_in[10]; const float* b_up2 = (const float*)d_in[11];
    const float* g_up1 = (const float*)d_in[12]; const float* b_up1 = (const float*)d_in[13];
    const float* g_up0 = (const float*)d_in[14]; const float* b_up0 = (const float*)d_in[15];
    const float* g_s0  = (const float*)d_in[16]; const float* b_s0  = (const float*)d_in[17];
    const float* g_s1  = (const float*)d_in[18]; const float* b_s1  = (const float*)d_in[19];
    const float* g_s2  = (const float*)d_in[20]; const float* b_s2  = (const float*)d_in[21];
    const int* up2_in = (const int*)d_in[22]; const int* up2_out = (const int*)d_in[23];
    const int* up1_in = (const int*)d_in[24]; const int* up1_out = (const int*)d_in[25];
    const int* up0_in = (const int*)d_in[26]; const int* up0_out = (const int*)d_in[27];
    const int* sm0_in = (const int*)d_in[28]; const int* sm0_out = (const int*)d_in[29];
    const int* sm1_in = (const int*)d_in[30]; const int* sm1_out = (const int*)d_in[31];

    float *acc, *bufA, *bufB, *wt, *sum, *sq, *scale, *shift;
    cudaGetSymbolAddress((void**)&acc,   g_acc);
    cudaGetSymbolAddress((void**)&bufA,  g_bufA);
    cudaGetSymbolAddress((void**)&bufB,  g_bufB);
    cudaGetSymbolAddress((void**)&wt,    g_wt);
    cudaGetSymbolAddress((void**)&sum,   g_sum);
    cudaGetSymbolAddress((void**)&sq,    g_sq);
    cudaGetSymbolAddress((void**)&scale, g_scale);
    cudaGetSymbolAddress((void**)&shift, g_shift);

    const int N0 = 30000, N1 = 12000, N2 = 5000;
    const int K = 27;

    // --- transpose all weights into pool ---
    float* wt_up2 = wt;
    float* wt_up1 = wt_up2 + (size_t)27 * 128 * 128;
    float* wt_up0 = wt_up1 + (size_t)27 * 192 * 192;
    float* wt_s0  = wt_up0 + (size_t)27 * 224 * 224;
    float* wt_s1  = wt_s0  + (size_t)27 * 240 * 512;
    float* wt_s2  = wt_s1  + (size_t)27 * 512 * 512;

    auto tlaunch = [&](const float* W, float* WT, int Cin, int Cout, int kk) {
        dim3 tg((Cout + 31) / 32, (Cin + 31) / 32, kk);
        transpose_kernel<<<tg, dim3(32, 8), 0, 0>>>(W, WT, Cin, Cout);
    };
    tlaunch(W_up2, wt_up2, 128, 128, K);
    tlaunch(W_up1, wt_up1, 192, 192, K);
    tlaunch(W_up0, wt_up0, 224, 224, K);
    tlaunch(W_s0,  wt_s0,  240, 512, K);
    tlaunch(W_s1,  wt_s1,  512, 512, K);
    tlaunch(W_s2,  wt_s2,  512, 512, 1);

    auto layer = [&](const float* A, const float* WT,
                     const int* ii, const int* oi,
                     int M, int Cin, int Cout, int Nout,
                     const float* gamma, const float* beta,
                     float* outbuf, int ostride,
                     const float* skip, int Cskip, int skip_N)
    {
        bool sparse = (oi != nullptr);
        float* dst = sparse ? acc : outbuf;   // dense final layer stores direct
        if (sparse)
            cudaMemsetAsync(acc, 0, (size_t)Nout * Cout * sizeof(float), 0);
        cudaMemsetAsync(sum, 0, Cout * sizeof(float), 0);
        cudaMemsetAsync(sq,  0, Cout * sizeof(float), 0);

        dim3 grid((M + 127) / 128, (Cout + 127) / 128, sparse ? K : 1);
        mma_gs_kernel<<<grid, 256, 0, 0>>>(A, WT, ii, oi, dst, M, Cin, Cout);

        stats_kernel<<<592, 256, 2 * Cout * sizeof(float), 0>>>(dst, Nout, Cout, sum, sq);
        bnparam_kernel<<<2, 256, 0, 0>>>(sum, sq, gamma, beta, Nout, Cout, scale, shift);
        bnapply_kernel<<<592, 256, 0, 0>>>(dst, Nout, Cout, ostride, scale, shift, outbuf);
        if (skip)
            copyskip_kernel<<<256, 256, 0, 0>>>(skip, skip_N, Cskip, ostride, Cout, outbuf);
    };

    // up2: f3 -> N2 (Cout 128), concat f2(64) -> bufA[5000,192]
    layer(f3,   wt_up2, up2_in, up2_out, 1600, 128, 128, N2, g_up2, b_up2, bufA, 192, f2, 64, N2);
    // up1: bufA -> N1 (Cout 192), concat f1(32) -> bufB[12000,224]
    layer(bufA, wt_up1, up1_in, up1_out, 4000, 192, 192, N1, g_up1, b_up1, bufB, 224, f1, 32, N1);
    // up0: bufB -> N0 (Cout 224), concat f0(16) -> bufA[30000,240]
    layer(bufB, wt_up0, up0_in, up0_out, 10000, 224, 224, N0, g_up0, b_up0, bufA, 240, f0, 16, N0);
    // s0: bufA[30000,240] -> N0 (Cout 512) -> bufB
    layer(bufA, wt_s0, sm0_in, sm0_out, 10000, 240, 512, N0, g_s0, b_s0, bufB, 512, nullptr, 0, 0);
    // s1: bufB -> N0 (Cout 512) -> bufA
    layer(bufB, wt_s1, sm1_in, sm1_out, 10000, 512, 512, N0, g_s1, b_s1, bufA, 512, nullptr, 0, 0);
    // s2: dense GEMM bufA @ W_s2 -> d_out
    layer(bufA, wt_s2, nullptr, nullptr, N0, 512, 512, N0, g_s2, b_s2, (float*)d_out, 512, nullptr, 0, 0);
}